// round 2
// baseline (speedup 1.0000x reference)
#include <cuda_runtime.h>
#include <math.h>

// Problem constants
#define Hd   128
#define Bg   512
#define Nn   8192
#define Ee   16384
#define EDIM 32

// ---------------- scratch (device globals; no allocation) ----------------
__device__ float g_transform[268435456];   // [E, H*H] = 1 GiB
__device__ float g_hmid[Ee * Hd];          // [E, 128]
__device__ float g_h[Nn * Hd];             // layer_input / hx  [N, 128]
__device__ float g_upd[Nn * Hd];           // scatter target     [N, 128]
__device__ float g_wihT[Hd * 384];         // gru w_ih transposed [j][t]
__device__ float g_whhT[Hd * 384];
__device__ float g_lihT[256 * 512];        // lstm w_ih transposed [j][t]
__device__ float g_lhhT[Hd * 512];
__device__ float g_hs[Bg * Hd];            // set2set h
__device__ float g_cs[Bg * Hd];            // set2set c
__device__ float g_qs[Bg * 256];           // q_star

__device__ __forceinline__ float sigm(float x) { return 1.0f / (1.0f + expf(-x)); }

// ---------------- init: node embedding gather ----------------
__global__ void k_init_h(const int* __restrict__ ut, const float* __restrict__ emb) {
    int n = blockIdx.x, t = threadIdx.x;
    g_h[n * Hd + t] = emb[ut[n] * Hd + t];
}

// ---------------- transpose recurrent weights (coalesced consumer reads) ----
__global__ void k_transpose(const float* __restrict__ gih, const float* __restrict__ ghh,
                            const float* __restrict__ lih, const float* __restrict__ lhh) {
    int i = blockIdx.x * blockDim.x + threadIdx.x;   // up to 512*256 = 131072
    if (i < 384 * 128) { int t = i / 128, j = i % 128; g_wihT[j * 384 + t] = gih[i]; g_whhT[j * 384 + t] = ghh[i]; }
    if (i < 512 * 256) { int t = i / 256, j = i % 256; g_lihT[j * 512 + t] = lih[i]; }
    if (i < 512 * 128) { int t = i / 128, j = i % 128; g_lhhT[j * 512 + t] = lhh[i]; }
}

// ---------------- edge hidden: hmid = relu(ef @ W1 + b1) ----------------
__global__ void k_edge_hidden(const float* __restrict__ ef, const float* __restrict__ w1,
                              const float* __restrict__ b1) {
    int e = blockIdx.x, t = threadIdx.x;
    __shared__ float efs[EDIM];
    if (t < EDIM) efs[t] = ef[e * EDIM + t];
    __syncthreads();
    float acc = b1[t];
#pragma unroll
    for (int k = 0; k < EDIM; k++) acc += efs[k] * w1[k * Hd + t];
    g_hmid[e * Hd + t] = fmaxf(acc, 0.0f);
}

// ---------------- big GEMM: transform = hmid @ W2 + b2 ----------------
// M = 16384 (edges), K = 128, N = 16384.  128x128 block tile, 8x8 per thread.
__global__ void __launch_bounds__(256) k_gemm(const float* __restrict__ Bm,
                                              const float* __restrict__ bias) {
    __shared__ float As[8][128];
    __shared__ float Bs[8][128];
    const int tid = threadIdx.x;              // 256
    const int tr = tid / 16, tc = tid % 16;
    const int rowBase = blockIdx.y * 128;
    const int colBase = blockIdx.x * 128;
    // A tile loads: 128 rows x 8 k, float4 along k. 2 float4 per row.
    const int aRow = tid / 2;
    const int aK   = (tid % 2) * 4;
    // B tile loads: 8 k x 128 cols, float4 along cols.
    const int bK = tid / 32;
    const int bC = (tid % 32) * 4;

    float acc[8][8];
#pragma unroll
    for (int u = 0; u < 8; u++)
#pragma unroll
        for (int v = 0; v < 8; v++) acc[u][v] = 0.0f;

    for (int k0 = 0; k0 < 128; k0 += 8) {
        float4 av = *(const float4*)&g_hmid[(rowBase + aRow) * 128 + k0 + aK];
        As[aK + 0][aRow] = av.x; As[aK + 1][aRow] = av.y;
        As[aK + 2][aRow] = av.z; As[aK + 3][aRow] = av.w;
        float4 bv = *(const float4*)&Bm[(size_t)(k0 + bK) * 16384 + colBase + bC];
        *(float4*)&Bs[bK][bC] = bv;
        __syncthreads();
#pragma unroll
        for (int kk = 0; kk < 8; kk++) {
            float ra[8], rb[8];
#pragma unroll
            for (int u = 0; u < 8; u++) ra[u] = As[kk][tr * 8 + u];
#pragma unroll
            for (int v = 0; v < 8; v++) rb[v] = Bs[kk][tc * 8 + v];
#pragma unroll
            for (int u = 0; u < 8; u++)
#pragma unroll
                for (int v = 0; v < 8; v++) acc[u][v] += ra[u] * rb[v];
        }
        __syncthreads();
    }
    const int c = colBase + tc * 8;
    float bia[8];
#pragma unroll
    for (int v = 0; v < 8; v++) bia[v] = bias[c + v];
#pragma unroll
    for (int u = 0; u < 8; u++) {
        size_t row = (size_t)(rowBase + tr * 8 + u);
        float4 o0, o1;
        o0.x = acc[u][0] + bia[0]; o0.y = acc[u][1] + bia[1];
        o0.z = acc[u][2] + bia[2]; o0.w = acc[u][3] + bia[3];
        o1.x = acc[u][4] + bia[4]; o1.y = acc[u][5] + bia[5];
        o1.z = acc[u][6] + bia[6]; o1.w = acc[u][7] + bia[7];
        *(float4*)&g_transform[row * 16384 + c]     = o0;
        *(float4*)&g_transform[row * 16384 + c + 4] = o1;
    }
}

// ---------------- zero helpers ----------------
__global__ void k_zero_upd() {
    int i = blockIdx.x * blockDim.x + threadIdx.x;
    if (i < Nn * Hd) g_upd[i] = 0.0f;
}
__global__ void k_zero_states() {
    int i = blockIdx.x * blockDim.x + threadIdx.x;  // 262144 total
    if (i < Bg * Hd)            g_hs[i] = 0.0f;
    else if (i < 2 * Bg * Hd)   g_cs[i - Bg * Hd] = 0.0f;
    else if (i < 4 * Bg * Hd)   g_qs[i - 2 * Bg * Hd] = 0.0f;
}

// ---------------- message: per-edge matvec + scatter ----------------
__global__ void k_message(const int* __restrict__ node_in, const int* __restrict__ node_out) {
    int e = blockIdx.x, t = threadIdx.x;
    __shared__ float v[Hd];
    int src = node_in[e];
    v[t] = g_h[src * Hd + t];
    __syncthreads();
    int lane = t & 31, w = t >> 5;
    int dst = node_out[e];
    const float* T = &g_transform[(size_t)e * 16384];
    float v0 = v[lane * 4 + 0], v1 = v[lane * 4 + 1], v2 = v[lane * 4 + 2], v3 = v[lane * 4 + 3];
#pragma unroll
    for (int r = w; r < Hd; r += 4) {
        float4 tv = *(const float4*)&T[r * Hd + lane * 4];
        float s = tv.x * v0 + tv.y * v1 + tv.z * v2 + tv.w * v3;
#pragma unroll
        for (int o = 16; o; o >>= 1) s += __shfl_down_sync(0xffffffffu, s, o);
        if (lane == 0) atomicAdd(&g_upd[dst * Hd + r], s);
    }
}

// ---------------- GRU: 4 nodes per block ----------------
__global__ void __launch_bounds__(128) k_gru(const float* __restrict__ b_ih,
                                             const float* __restrict__ b_hh) {
    int n0 = blockIdx.x * 4;
    int t = threadIdx.x;
    __shared__ float xs[4][Hd];
    __shared__ float hs[4][Hd];
#pragma unroll
    for (int q = 0; q < 4; q++) {
        xs[q][t] = fmaxf(g_upd[(n0 + q) * Hd + t], 0.0f);
        hs[q][t] = g_h[(n0 + q) * Hd + t];
    }
    __syncthreads();
    float ir[4], iz[4], in_[4], hr[4], hz[4], hn[4];
    float bir = b_ih[t], biz = b_ih[128 + t], bin = b_ih[256 + t];
    float bhr = b_hh[t], bhz = b_hh[128 + t], bhn = b_hh[256 + t];
#pragma unroll
    for (int q = 0; q < 4; q++) { ir[q] = bir; iz[q] = biz; in_[q] = bin; hr[q] = bhr; hz[q] = bhz; hn[q] = bhn; }
    for (int j = 0; j < Hd; j++) {
        float wi0 = g_wihT[j * 384 + t], wi1 = g_wihT[j * 384 + 128 + t], wi2 = g_wihT[j * 384 + 256 + t];
        float wh0 = g_whhT[j * 384 + t], wh1 = g_whhT[j * 384 + 128 + t], wh2 = g_whhT[j * 384 + 256 + t];
#pragma unroll
        for (int q = 0; q < 4; q++) {
            float x = xs[q][j], h = hs[q][j];
            ir[q] += x * wi0; iz[q] += x * wi1; in_[q] += x * wi2;
            hr[q] += h * wh0; hz[q] += h * wh1; hn[q] += h * wh2;
        }
    }
#pragma unroll
    for (int q = 0; q < 4; q++) {
        float r = sigm(ir[q] + hr[q]);
        float z = sigm(iz[q] + hz[q]);
        float nn = tanhf(in_[q] + r * hn[q]);
        g_h[(n0 + q) * Hd + t] = (1.0f - z) * nn + z * hs[q][t];
    }
}

// ---------------- LSTM step (Set2Set) ----------------
__global__ void k_lstm(const float* __restrict__ b_ih, const float* __restrict__ b_hh) {
    int b = blockIdx.x, t = threadIdx.x;
    __shared__ float qs[256];
    __shared__ float hsm[Hd];
    qs[t] = g_qs[b * 256 + t];
    qs[128 + t] = g_qs[b * 256 + 128 + t];
    hsm[t] = g_hs[b * Hd + t];
    __syncthreads();
    float gi = b_ih[t] + b_hh[t];
    float gf = b_ih[128 + t] + b_hh[128 + t];
    float gg = b_ih[256 + t] + b_hh[256 + t];
    float go = b_ih[384 + t] + b_hh[384 + t];
    for (int j = 0; j < 256; j++) {
        float q = qs[j];
        const float* wi = &g_lihT[j * 512];
        gi += q * wi[t]; gf += q * wi[128 + t]; gg += q * wi[256 + t]; go += q * wi[384 + t];
    }
    for (int j = 0; j < Hd; j++) {
        float h = hsm[j];
        const float* wh = &g_lhhT[j * 512];
        gi += h * wh[t]; gf += h * wh[128 + t]; gg += h * wh[256 + t]; go += h * wh[384 + t];
    }
    float c = sigm(gf) * g_cs[b * Hd + t] + sigm(gi) * tanhf(gg);
    float h = sigm(go) * tanhf(c);
    g_cs[b * Hd + t] = c;
    g_hs[b * Hd + t] = h;
}

// ---------------- attention + pooled (exact online segment softmax) ----------
__global__ void k_attend(const int* __restrict__ n2g) {
    int b = blockIdx.x, t = threadIdx.x;
    __shared__ float hsm[Hd];
    __shared__ float red[4];
    __shared__ int seg[2];
    hsm[t] = g_hs[b * Hd + t];
    if (t == 0) {
        int lo = 0, hi = Nn;
        while (lo < hi) { int m = (lo + hi) >> 1; if (n2g[m] < b) lo = m + 1; else hi = m; }
        seg[0] = lo;
        int lo2 = lo, hi2 = Nn;
        while (lo2 < hi2) { int m = (lo2 + hi2) >> 1; if (n2g[m] < b + 1) lo2 = m + 1; else hi2 = m; }
        seg[1] = lo2;
    }
    __syncthreads();
    int lo = seg[0], hi = seg[1];
    float m = -INFINITY, s = 0.0f, pool = 0.0f;
    for (int idx = lo; idx < hi; idx++) {
        float nf = g_h[(size_t)idx * Hd + t];
        float part = hsm[t] * nf;
#pragma unroll
        for (int o = 16; o; o >>= 1) part += __shfl_down_sync(0xffffffffu, part, o);
        if ((t & 31) == 0) red[t >> 5] = part;
        __syncthreads();
        float p = red[0] + red[1] + red[2] + red[3];
        __syncthreads();
        float mn = fmaxf(m, p);
        float corr = expf(m - mn);   // exp(-inf) = 0 on first iter
        float w = expf(p - mn);
        s = s * corr + w;
        pool = pool * corr + w * nf;
        m = mn;
    }
    float pooled = (s > 0.0f) ? pool / s : 0.0f;
    g_qs[b * 256 + t] = hsm[t];
    g_qs[b * 256 + 128 + t] = pooled;
}

// ---------------- final output: [q_star (B*2H), node_feature (N*H)] --------
__global__ void k_copy_out(float* __restrict__ out) {
    int i = blockIdx.x * blockDim.x + threadIdx.x;
    if (i < Bg * 256) out[i] = g_qs[i];
    else if (i < Bg * 256 + Nn * Hd) out[i] = g_h[i - Bg * 256];
}

extern "C" void kernel_launch(void* const* d_in, const int* in_sizes, int n_in,
                              void* d_out, int out_size) {
    const int*   unit_type    = (const int*)d_in[0];
    const int*   node_in      = (const int*)d_in[1];
    const int*   node_out     = (const int*)d_in[2];
    const int*   node2graph   = (const int*)d_in[3];
    const float* edge_feature = (const float*)d_in[4];
    const float* embedding    = (const float*)d_in[5];
    const float* mlp_w1       = (const float*)d_in[6];
    const float* mlp_b1       = (const float*)d_in[7];
    const float* mlp_w2       = (const float*)d_in[8];
    const float* mlp_b2       = (const float*)d_in[9];
    const float* gru_w_ih     = (const float*)d_in[10];
    const float* gru_w_hh     = (const float*)d_in[11];
    const float* gru_b_ih     = (const float*)d_in[12];
    const float* gru_b_hh     = (const float*)d_in[13];
    const float* lstm_w_ih    = (const float*)d_in[14];
    const float* lstm_w_hh    = (const float*)d_in[15];
    const float* lstm_b_ih    = (const float*)d_in[16];
    const float* lstm_b_hh    = (const float*)d_in[17];

    k_init_h<<<Nn, Hd>>>(unit_type, embedding);
    k_transpose<<<512, 256>>>(gru_w_ih, gru_w_hh, lstm_w_ih, lstm_w_hh);
    k_edge_hidden<<<Ee, Hd>>>(edge_feature, mlp_w1, mlp_b1);
    k_gemm<<<dim3(128, 128), 256>>>(mlp_w2, mlp_b2);

    for (int l = 0; l < 3; l++) {
        k_zero_upd<<<(Nn * Hd + 255) / 256, 256>>>();
        k_message<<<Ee, Hd>>>(node_in, node_out);
        k_gru<<<Nn / 4, Hd>>>(gru_b_ih, gru_b_hh);
    }

    k_zero_states<<<(4 * Bg * Hd + 255) / 256, 256>>>();
    for (int s = 0; s < 3; s++) {
        k_lstm<<<Bg, Hd>>>(lstm_b_ih, lstm_b_hh);
        k_attend<<<Bg, Hd>>>(node2graph);
    }

    int total = Bg * 256 + Nn * Hd;
    k_copy_out<<<(total + 255) / 256, 256>>>((float*)d_out);
}

// round 5
// speedup vs baseline: 1.9011x; 1.9011x over previous
#include <cuda_runtime.h>
#include <cuda_bf16.h>
#include <cstdint>
#include <math.h>

// Problem constants
#define Hd   128
#define Bg   512
#define Nn   8192
#define Ee   16384
#define EDIM 32

// ---------------- scratch (device globals; no allocation) ----------------
__device__ float g_transform[268435456];   // [E, H*H] = 1 GiB
__device__ __nv_bfloat16 g_hmid_hi[Ee * Hd];
__device__ __nv_bfloat16 g_hmid_lo[Ee * Hd];
__device__ __nv_bfloat16 g_w2T_hi[16384 * 128];   // [N, K] = W2 transposed
__device__ __nv_bfloat16 g_w2T_lo[16384 * 128];
__device__ float g_h[Nn * Hd];             // layer_input / hx  [N, 128]
__device__ float g_upd[Nn * Hd];           // scatter target     [N, 128]
__device__ float g_wihT[Hd * 384];         // gru w_ih transposed [j][t]
__device__ float g_whhT[Hd * 384];
__device__ float g_lihT[256 * 512];        // lstm w_ih transposed [j][t]
__device__ float g_lhhT[Hd * 512];
__device__ float g_hs[Bg * Hd];            // set2set h
__device__ float g_cs[Bg * Hd];            // set2set c
__device__ float g_qs[Bg * 256];           // q_star

__device__ __forceinline__ float sigm(float x) { return 1.0f / (1.0f + expf(-x)); }

__device__ __forceinline__ uint32_t smem_u32(const void* p) {
    uint32_t a;
    asm("{ .reg .u64 t; cvta.to.shared.u64 t, %1; cvt.u32.u64 %0, t; }" : "=r"(a) : "l"(p));
    return a;
}

#define LDSM_X4(r, a) \
    asm volatile("ldmatrix.sync.aligned.m8n8.x4.shared.b16 {%0,%1,%2,%3}, [%4];" \
        : "=r"((r)[0]), "=r"((r)[1]), "=r"((r)[2]), "=r"((r)[3]) : "r"(a))

__device__ __forceinline__ void mma16816(float* c, const uint32_t* a, uint32_t b0, uint32_t b1) {
    asm volatile("mma.sync.aligned.m16n8k16.row.col.f32.bf16.bf16.f32 "
        "{%0,%1,%2,%3}, {%4,%5,%6,%7}, {%8,%9}, {%0,%1,%2,%3};"
        : "+f"(c[0]), "+f"(c[1]), "+f"(c[2]), "+f"(c[3])
        : "r"(a[0]), "r"(a[1]), "r"(a[2]), "r"(a[3]), "r"(b0), "r"(b1));
}

// ---------------- init: node embedding gather ----------------
__global__ void k_init_h(const int* __restrict__ ut, const float* __restrict__ emb) {
    int n = blockIdx.x, t = threadIdx.x;
    g_h[n * Hd + t] = emb[ut[n] * Hd + t];
}

// ---------------- transpose recurrent weights ----------------
__global__ void k_transpose(const float* __restrict__ gih, const float* __restrict__ ghh,
                            const float* __restrict__ lih, const float* __restrict__ lhh) {
    int i = blockIdx.x * blockDim.x + threadIdx.x;
    if (i < 384 * 128) { int t = i / 128, j = i % 128; g_wihT[j * 384 + t] = gih[i]; g_whhT[j * 384 + t] = ghh[i]; }
    if (i < 512 * 256) { int t = i / 256, j = i % 256; g_lihT[j * 512 + t] = lih[i]; }
    if (i < 512 * 128) { int t = i / 128, j = i % 128; g_lhhT[j * 512 + t] = lhh[i]; }
}

// ---------------- edge hidden: hmid = relu(ef @ W1 + b1), split to bf16 hi/lo
__global__ void k_edge_hidden(const float* __restrict__ ef, const float* __restrict__ w1,
                              const float* __restrict__ b1) {
    int e = blockIdx.x, t = threadIdx.x;
    __shared__ float efs[EDIM];
    if (t < EDIM) efs[t] = ef[e * EDIM + t];
    __syncthreads();
    float acc = b1[t];
#pragma unroll
    for (int k = 0; k < EDIM; k++) acc += efs[k] * w1[k * Hd + t];
    acc = fmaxf(acc, 0.0f);
    __nv_bfloat16 hi = __float2bfloat16(acc);
    float r = acc - __bfloat162float(hi);
    g_hmid_hi[e * Hd + t] = hi;
    g_hmid_lo[e * Hd + t] = __float2bfloat16(r);
}

// ---------------- W2 transpose + bf16 split: [128,16384] -> [16384,128] ------
__global__ void k_w2t(const float* __restrict__ w2) {
    int i = blockIdx.x * blockDim.x + threadIdx.x;   // 2097152 elems
    int k = i >> 14, n = i & 16383;
    float v = w2[i];
    __nv_bfloat16 hi = __float2bfloat16(v);
    float r = v - __bfloat162float(hi);
    g_w2T_hi[(size_t)n * 128 + k] = hi;
    g_w2T_lo[(size_t)n * 128 + k] = __float2bfloat16(r);
}

// ---------------- mma.sync GEMM: transform = hmid @ W2 + b2 ------------------
// Block 128x128, K=128 resident. 8 warps, warp tile 32x64.
// SMEM: As(Ah) 32KB | Bs(Bh) 32KB | Xs(Bl, then Al) 32KB = 96KB -> 2 blocks/SM.
// Split-bf16: acc = ah*bh + ah*bl + al*bh.
__global__ void __launch_bounds__(256) k_gemm_mma(const float* __restrict__ bias) {
    extern __shared__ char sm[];
    char* As = sm;
    char* Bs = sm + 32768;
    char* Xs = sm + 65536;

    const int tid = threadIdx.x;
    const int wid = tid >> 5, l = tid & 31;
    const int wm = wid & 3, wn = wid >> 2;            // 4 x 2 warp grid
    const int rowBase = blockIdx.y * 128;
    const int colBase = blockIdx.x * 128;

    // cooperative tile load with swizzle: off = r*256 + kk*16, XOR (r&7)<<4
    {
        const uint4* Ah = (const uint4*)g_hmid_hi + (size_t)rowBase * 16;
        const uint4* Bh = (const uint4*)g_w2T_hi + (size_t)colBase * 16;
        const uint4* Bl = (const uint4*)g_w2T_lo + (size_t)colBase * 16;
        for (int i = tid; i < 2048; i += 256) {
            int r = i >> 4, kk = i & 15;
            uint32_t off = ((uint32_t)r << 8) + ((uint32_t)kk << 4);
            off ^= (r & 7) << 4;
            *(uint4*)(As + off) = Ah[i];
            *(uint4*)(Bs + off) = Bh[i];
            *(uint4*)(Xs + off) = Bl[i];
        }
    }
    __syncthreads();

    uint32_t aBase = smem_u32(As), bBase = smem_u32(Bs), xBase = smem_u32(Xs);

    float acc[2][8][4];
#pragma unroll
    for (int mf = 0; mf < 2; mf++)
#pragma unroll
        for (int nf = 0; nf < 8; nf++)
#pragma unroll
            for (int q = 0; q < 4; q++) acc[mf][nf][q] = 0.0f;

    // per-lane ldmatrix roles
    const int rA = l & 15;                 // A: row within 16
    const int ksA = (l >> 4) & 1;          // A: k-half (0/1 -> +0/+8)
    const int nAdd = (l & 7) + ((l >> 4) << 3);   // B: n offset within 16
    const int kAdd = ((l >> 3) & 1) << 3;         // B: k-half

#define DO_PASS(AB, BB)                                                          \
    _Pragma("unroll")                                                            \
    for (int ks = 0; ks < 8; ks++) {                                             \
        const int k0 = ks * 16;                                                  \
        uint32_t ra[2][4];                                                       \
        _Pragma("unroll")                                                        \
        for (int mf = 0; mf < 2; mf++) {                                         \
            int r = wm * 32 + mf * 16 + rA;                                      \
            uint32_t off = ((uint32_t)r << 8) + (uint32_t)((k0 + ksA * 8) << 1); \
            off ^= (r & 7) << 4;                                                 \
            LDSM_X4(ra[mf], (AB) + off);                                         \
        }                                                                        \
        uint32_t rb[4][4];                                                       \
        _Pragma("unroll")                                                        \
        for (int q = 0; q < 4; q++) {                                            \
            int n = wn * 64 + q * 16 + nAdd;                                     \
            uint32_t off = ((uint32_t)n << 8) + (uint32_t)((k0 + kAdd) << 1);    \
            off ^= (n & 7) << 4;                                                 \
            LDSM_X4(rb[q], (BB) + off);                                          \
        }                                                                        \
        _Pragma("unroll")                                                        \
        for (int mf = 0; mf < 2; mf++)                                           \
            _Pragma("unroll")                                                    \
            for (int q = 0; q < 4; q++) {                                        \
                mma16816(acc[mf][2 * q],     ra[mf], rb[q][0], rb[q][1]);        \
                mma16816(acc[mf][2 * q + 1], ra[mf], rb[q][2], rb[q][3]);        \
            }                                                                    \
    }

    DO_PASS(aBase, bBase);   // ah * bh
    DO_PASS(aBase, xBase);   // ah * bl
    __syncthreads();
    // reload X with Al
    {
        const uint4* Al = (const uint4*)g_hmid_lo + (size_t)rowBase * 16;
        for (int i = tid; i < 2048; i += 256) {
            int r = i >> 4, kk = i & 15;
            uint32_t off = ((uint32_t)r << 8) + ((uint32_t)kk << 4);
            off ^= (r & 7) << 4;
            *(uint4*)(Xs + off) = Al[i];
        }
    }
    __syncthreads();
    DO_PASS(xBase, bBase);   // al * bh
#undef DO_PASS

    // epilogue: bias add + store
    const int colW = colBase + wn * 64;
#pragma unroll
    for (int mf = 0; mf < 2; mf++) {
        int row = rowBase + wm * 32 + mf * 16 + (l >> 2);
#pragma unroll
        for (int nf = 0; nf < 8; nf++) {
            int col = colW + nf * 8 + (l & 3) * 2;
            float b0 = bias[col], b1 = bias[col + 1];
            float2 o0 = {acc[mf][nf][0] + b0, acc[mf][nf][1] + b1};
            float2 o1 = {acc[mf][nf][2] + b0, acc[mf][nf][3] + b1};
            *(float2*)&g_transform[(size_t)row * 16384 + col] = o0;
            *(float2*)&g_transform[(size_t)(row + 8) * 16384 + col] = o1;
        }
    }
}

// ---------------- zero helpers ----------------
__global__ void k_zero_upd() {
    int i = blockIdx.x * blockDim.x + threadIdx.x;
    if (i < Nn * Hd) g_upd[i] = 0.0f;
}
__global__ void k_zero_states() {
    int i = blockIdx.x * blockDim.x + threadIdx.x;
    if (i < Bg * Hd)            g_hs[i] = 0.0f;
    else if (i < 2 * Bg * Hd)   g_cs[i - Bg * Hd] = 0.0f;
    else if (i < 4 * Bg * Hd)   g_qs[i - 2 * Bg * Hd] = 0.0f;
}

// ---------------- message: per-edge matvec + scatter ----------------
__global__ void k_message(const int* __restrict__ node_in, const int* __restrict__ node_out) {
    int e = blockIdx.x, t = threadIdx.x;
    __shared__ float v[Hd];
    int src = node_in[e];
    v[t] = g_h[src * Hd + t];
    __syncthreads();
    int lane = t & 31, w = t >> 5;
    int dst = node_out[e];
    const float* T = &g_transform[(size_t)e * 16384];
    float v0 = v[lane * 4 + 0], v1 = v[lane * 4 + 1], v2 = v[lane * 4 + 2], v3 = v[lane * 4 + 3];
#pragma unroll
    for (int r = w; r < Hd; r += 4) {
        float4 tv = *(const float4*)&T[r * Hd + lane * 4];
        float s = tv.x * v0 + tv.y * v1 + tv.z * v2 + tv.w * v3;
#pragma unroll
        for (int o = 16; o; o >>= 1) s += __shfl_down_sync(0xffffffffu, s, o);
        if (lane == 0) atomicAdd(&g_upd[dst * Hd + r], s);
    }
}

// ---------------- GRU: 8 nodes per block ----------------
__global__ void __launch_bounds__(128) k_gru(const float* __restrict__ b_ih,
                                             const float* __restrict__ b_hh) {
    int n0 = blockIdx.x * 8;
    int t = threadIdx.x;
    __shared__ float xs[8][Hd];
    __shared__ float hs[8][Hd];
#pragma unroll
    for (int q = 0; q < 8; q++) {
        xs[q][t] = fmaxf(g_upd[(n0 + q) * Hd + t], 0.0f);
        hs[q][t] = g_h[(n0 + q) * Hd + t];
    }
    __syncthreads();
    float ir[8], iz[8], in_[8], hr[8], hz[8], hn[8];
    float bir = b_ih[t], biz = b_ih[128 + t], bin = b_ih[256 + t];
    float bhr = b_hh[t], bhz = b_hh[128 + t], bhn = b_hh[256 + t];
#pragma unroll
    for (int q = 0; q < 8; q++) { ir[q] = bir; iz[q] = biz; in_[q] = bin; hr[q] = bhr; hz[q] = bhz; hn[q] = bhn; }
    for (int j = 0; j < Hd; j++) {
        float wi0 = g_wihT[j * 384 + t], wi1 = g_wihT[j * 384 + 128 + t], wi2 = g_wihT[j * 384 + 256 + t];
        float wh0 = g_whhT[j * 384 + t], wh1 = g_whhT[j * 384 + 128 + t], wh2 = g_whhT[j * 384 + 256 + t];
#pragma unroll
        for (int q = 0; q < 8; q++) {
            float x = xs[q][j], h = hs[q][j];
            ir[q] += x * wi0; iz[q] += x * wi1; in_[q] += x * wi2;
            hr[q] += h * wh0; hz[q] += h * wh1; hn[q] += h * wh2;
        }
    }
#pragma unroll
    for (int q = 0; q < 8; q++) {
        float r = sigm(ir[q] + hr[q]);
        float z = sigm(iz[q] + hz[q]);
        float nn = tanhf(in_[q] + r * hn[q]);
        g_h[(n0 + q) * Hd + t] = (1.0f - z) * nn + z * hs[q][t];
    }
}

// ---------------- LSTM step (Set2Set) ----------------
__global__ void k_lstm(const float* __restrict__ b_ih, const float* __restrict__ b_hh) {
    int b = blockIdx.x, t = threadIdx.x;
    __shared__ float qs[256];
    __shared__ float hsm[Hd];
    qs[t] = g_qs[b * 256 + t];
    qs[128 + t] = g_qs[b * 256 + 128 + t];
    hsm[t] = g_hs[b * Hd + t];
    __syncthreads();
    float gi = b_ih[t] + b_hh[t];
    float gf = b_ih[128 + t] + b_hh[128 + t];
    float gg = b_ih[256 + t] + b_hh[256 + t];
    float go = b_ih[384 + t] + b_hh[384 + t];
    for (int j = 0; j < 256; j++) {
        float q = qs[j];
        const float* wi = &g_lihT[j * 512];
        gi += q * wi[t]; gf += q * wi[128 + t]; gg += q * wi[256 + t]; go += q * wi[384 + t];
    }
    for (int j = 0; j < Hd; j++) {
        float h = hsm[j];
        const float* wh = &g_lhhT[j * 512];
        gi += h * wh[t]; gf += h * wh[128 + t]; gg += h * wh[256 + t]; go += h * wh[384 + t];
    }
    float c = sigm(gf) * g_cs[b * Hd + t] + sigm(gi) * tanhf(gg);
    float h = sigm(go) * tanhf(c);
    g_cs[b * Hd + t] = c;
    g_hs[b * Hd + t] = h;
}

// ---------------- attention + pooled (exact online segment softmax) ----------
__global__ void k_attend(const int* __restrict__ n2g) {
    int b = blockIdx.x, t = threadIdx.x;
    __shared__ float hsm[Hd];
    __shared__ float red[4];
    __shared__ int seg[2];
    hsm[t] = g_hs[b * Hd + t];
    if (t == 0) {
        int lo = 0, hi = Nn;
        while (lo < hi) { int m = (lo + hi) >> 1; if (n2g[m] < b) lo = m + 1; else hi = m; }
        seg[0] = lo;
        int lo2 = lo, hi2 = Nn;
        while (lo2 < hi2) { int m = (lo2 + hi2) >> 1; if (n2g[m] < b + 1) lo2 = m + 1; else hi2 = m; }
        seg[1] = lo2;
    }
    __syncthreads();
    int lo = seg[0], hi = seg[1];
    float m = -INFINITY, s = 0.0f, pool = 0.0f;
    for (int idx = lo; idx < hi; idx++) {
        float nf = g_h[(size_t)idx * Hd + t];
        float part = hsm[t] * nf;
#pragma unroll
        for (int o = 16; o; o >>= 1) part += __shfl_down_sync(0xffffffffu, part, o);
        if ((t & 31) == 0) red[t >> 5] = part;
        __syncthreads();
        float p = red[0] + red[1] + red[2] + red[3];
        __syncthreads();
        float mn = fmaxf(m, p);
        float corr = expf(m - mn);
        float w = expf(p - mn);
        s = s * corr + w;
        pool = pool * corr + w * nf;
        m = mn;
    }
    float pooled = (s > 0.0f) ? pool / s : 0.0f;
    g_qs[b * 256 + t] = hsm[t];
    g_qs[b * 256 + 128 + t] = pooled;
}

// ---------------- final output ----------------
__global__ void k_copy_out(float* __restrict__ out) {
    int i = blockIdx.x * blockDim.x + threadIdx.x;
    if (i < Bg * 256) out[i] = g_qs[i];
    else if (i < Bg * 256 + Nn * Hd) out[i] = g_h[i - Bg * 256];
}

extern "C" void kernel_launch(void* const* d_in, const int* in_sizes, int n_in,
                              void* d_out, int out_size) {
    const int*   unit_type    = (const int*)d_in[0];
    const int*   node_in      = (const int*)d_in[1];
    const int*   node_out     = (const int*)d_in[2];
    const int*   node2graph   = (const int*)d_in[3];
    const float* edge_feature = (const float*)d_in[4];
    const float* embedding    = (const float*)d_in[5];
    const float* mlp_w1       = (const float*)d_in[6];
    const float* mlp_b1       = (const float*)d_in[7];
    const float* mlp_w2       = (const float*)d_in[8];
    const float* mlp_b2       = (const float*)d_in[9];
    const float* gru_w_ih     = (const float*)d_in[10];
    const float* gru_w_hh     = (const float*)d_in[11];
    const float* gru_b_ih     = (const float*)d_in[12];
    const float* gru_b_hh     = (const float*)d_in[13];
    const float* lstm_w_ih    = (const float*)d_in[14];
    const float* lstm_w_hh    = (const float*)d_in[15];
    const float* lstm_b_ih    = (const float*)d_in[16];
    const float* lstm_b_hh    = (const float*)d_in[17];

    cudaFuncSetAttribute(k_gemm_mma, cudaFuncAttributeMaxDynamicSharedMemorySize, 98304);

    k_init_h<<<Nn, Hd>>>(unit_type, embedding);
    k_transpose<<<512, 256>>>(gru_w_ih, gru_w_hh, lstm_w_ih, lstm_w_hh);
    k_edge_hidden<<<Ee, Hd>>>(edge_feature, mlp_w1, mlp_b1);
    k_w2t<<<8192, 256>>>(mlp_w2);
    k_gemm_mma<<<dim3(128, 128), 256, 98304>>>(mlp_b2);

    for (int l = 0; l < 3; l++) {
        k_zero_upd<<<(Nn * Hd + 255) / 256, 256>>>();
        k_message<<<Ee, Hd>>>(node_in, node_out);
        k_gru<<<Nn / 8, Hd>>>(gru_b_ih, gru_b_hh);
    }

    k_zero_states<<<(4 * Bg * Hd + 255) / 256, 256>>>();
    for (int s = 0; s < 3; s++) {
        k_lstm<<<Bg, Hd>>>(lstm_b_ih, lstm_b_hh);
        k_attend<<<Bg, Hd>>>(node2graph);
    }

    int total = Bg * 256 + Nn * Hd;
    k_copy_out<<<(total + 255) / 256, 256>>>((float*)d_out);
}

// round 6
// speedup vs baseline: 1.9347x; 1.0177x over previous
#include <cuda_runtime.h>
#include <cuda_bf16.h>
#include <cstdint>
#include <math.h>

// Problem constants
#define Hd   128
#define Bg   512
#define Nn   8192
#define Ee   16384
#define EDIM 32

// ---------------- scratch (device globals; no allocation) ----------------
__device__ float g_transform[268435456];   // [E, H*H] = 1 GiB
__device__ __nv_bfloat16 g_hmid_hi[Ee * Hd];
__device__ __nv_bfloat16 g_hmid_lo[Ee * Hd];
__device__ __nv_bfloat16 g_w2T_hi[16384 * 128];   // [N, K] = W2 transposed
__device__ __nv_bfloat16 g_w2T_lo[16384 * 128];
__device__ float g_h[Nn * Hd];             // layer_input / hx  [N, 128]
__device__ float g_upd[Nn * Hd];           // scatter target     [N, 128]
__device__ float g_wihT[Hd * 384];         // gru w_ih transposed [j][t]
__device__ float g_whhT[Hd * 384];
__device__ float g_lihT[256 * 512];        // lstm w_ih transposed [j][t]
__device__ float g_lhhT[Hd * 512];
__device__ float g_hs[Bg * Hd];            // set2set h
__device__ float g_cs[Bg * Hd];            // set2set c
__device__ float g_qs[Bg * 256];           // q_star

__device__ __forceinline__ float sigm(float x) { return 1.0f / (1.0f + expf(-x)); }

__device__ __forceinline__ uint32_t smem_u32(const void* p) {
    uint32_t a;
    asm("{ .reg .u64 t; cvta.to.shared.u64 t, %1; cvt.u32.u64 %0, t; }" : "=r"(a) : "l"(p));
    return a;
}

#define LDSM_X4(r, a) \
    asm volatile("ldmatrix.sync.aligned.m8n8.x4.shared.b16 {%0,%1,%2,%3}, [%4];" \
        : "=r"((r)[0]), "=r"((r)[1]), "=r"((r)[2]), "=r"((r)[3]) : "r"(a))

__device__ __forceinline__ void mma16816(float* c, const uint32_t* a, uint32_t b0, uint32_t b1) {
    asm volatile("mma.sync.aligned.m16n8k16.row.col.f32.bf16.bf16.f32 "
        "{%0,%1,%2,%3}, {%4,%5,%6,%7}, {%8,%9}, {%0,%1,%2,%3};"
        : "+f"(c[0]), "+f"(c[1]), "+f"(c[2]), "+f"(c[3])
        : "r"(a[0]), "r"(a[1]), "r"(a[2]), "r"(a[3]), "r"(b0), "r"(b1));
}

// ---------------- init: node embedding gather ----------------
__global__ void k_init_h(const int* __restrict__ ut, const float* __restrict__ emb) {
    int n = blockIdx.x, t = threadIdx.x;
    g_h[n * Hd + t] = emb[ut[n] * Hd + t];
}

// ---------------- prep: W2 transpose/split + weight transposes + zeroing -----
// blocks [0, 2048): tiled W2 transpose (32k x 32n tiles)
// blocks [2048, 8128): grid-linear misc (gru/lstm transposes, zero upd/states)
__global__ void __launch_bounds__(256) k_prep(const float* __restrict__ w2,
        const float* __restrict__ gih, const float* __restrict__ ghh,
        const float* __restrict__ lih, const float* __restrict__ lhh) {
    int bid = blockIdx.x, tid = threadIdx.x;
    if (bid < 2048) {
        __shared__ float ts[32][33];
        int kt = (bid & 3) * 32, nt = (bid >> 2) * 32;
        int r = tid >> 3, c4 = (tid & 7) * 4;
        const float4 v = *(const float4*)&w2[(size_t)(kt + r) * 16384 + nt + c4];
        ts[r][c4] = v.x; ts[r][c4 + 1] = v.y; ts[r][c4 + 2] = v.z; ts[r][c4 + 3] = v.w;
        __syncthreads();
        int n = nt + r;
        __nv_bfloat16 hi[4], lo[4];
#pragma unroll
        for (int q = 0; q < 4; q++) {
            float val = ts[c4 + q][r];
            hi[q] = __float2bfloat16(val);
            lo[q] = __float2bfloat16(val - __bfloat162float(hi[q]));
        }
        *(uint2*)&g_w2T_hi[(size_t)n * 128 + kt + c4] = *(uint2*)hi;
        *(uint2*)&g_w2T_lo[(size_t)n * 128 + kt + c4] = *(uint2*)lo;
        return;
    }
    long i = (long)(bid - 2048) * 256 + tid;
    if (i < 49152) { int t = i / 128, j = i % 128; g_wihT[j * 384 + t] = gih[i]; g_whhT[j * 384 + t] = ghh[i]; return; }
    i -= 49152;
    if (i < 131072) { int t = i / 256, j = i % 256; g_lihT[j * 512 + t] = lih[i]; return; }
    i -= 131072;
    if (i < 65536) { int t = i / 128, j = i % 128; g_lhhT[j * 512 + t] = lhh[i]; return; }
    i -= 65536;
    if (i < Nn * Hd) { g_upd[i] = 0.0f; return; }
    i -= Nn * Hd;
    if (i < Bg * Hd) { g_hs[i] = 0.0f; return; }
    i -= Bg * Hd;
    if (i < Bg * Hd) { g_cs[i] = 0.0f; return; }
    i -= Bg * Hd;
    if (i < Bg * 256) { g_qs[i] = 0.0f; return; }
}

// ---------------- edge hidden: hmid = relu(ef @ W1 + b1), split to bf16 hi/lo
__global__ void k_edge_hidden(const float* __restrict__ ef, const float* __restrict__ w1,
                              const float* __restrict__ b1) {
    int e = blockIdx.x, t = threadIdx.x;
    __shared__ float efs[EDIM];
    if (t < EDIM) efs[t] = ef[e * EDIM + t];
    __syncthreads();
    float acc = b1[t];
#pragma unroll
    for (int k = 0; k < EDIM; k++) acc += efs[k] * w1[k * Hd + t];
    acc = fmaxf(acc, 0.0f);
    __nv_bfloat16 hi = __float2bfloat16(acc);
    float r = acc - __bfloat162float(hi);
    g_hmid_hi[e * Hd + t] = hi;
    g_hmid_lo[e * Hd + t] = __float2bfloat16(r);
}

// ---------------- mma.sync GEMM + fused layer-1 message ---------------------
// Block 128(edges) x 128(cols); col tile = one full i (col = i*128 + j).
// Split-bf16 3 passes. Epilogue: store T (streaming), and msg1[e][i] =
// sum_j T[e,i,j] * x[node_in[e]][j] scattered into g_upd[node_out[e]][i].
__global__ void __launch_bounds__(256, 2) k_gemm_mma(const float* __restrict__ bias,
        const int* __restrict__ node_in, const int* __restrict__ node_out) {
    extern __shared__ char sm[];
    char* As = sm;
    char* Bs = sm + 32768;
    char* Xs = sm + 65536;

    const int tid = threadIdx.x;
    const int wid = tid >> 5, l = tid & 31;
    const int wm = wid & 3, wn = wid >> 2;            // 4 x 2 warp grid
    const int rowBase = blockIdx.y * 128;
    const int colBase = blockIdx.x * 128;

    // cooperative tile load with swizzle: off = r*256 + kk*16, XOR (r&7)<<4
    {
        const uint4* Ah = (const uint4*)g_hmid_hi + (size_t)rowBase * 16;
        const uint4* Bh = (const uint4*)g_w2T_hi + (size_t)colBase * 16;
        const uint4* Bl = (const uint4*)g_w2T_lo + (size_t)colBase * 16;
        for (int i = tid; i < 2048; i += 256) {
            int r = i >> 4, kk = i & 15;
            uint32_t off = ((uint32_t)r << 8) + ((uint32_t)kk << 4);
            off ^= (r & 7) << 4;
            *(uint4*)(As + off) = Ah[i];
            *(uint4*)(Bs + off) = Bh[i];
            *(uint4*)(Xs + off) = Bl[i];
        }
    }
    __syncthreads();

    uint32_t aBase = smem_u32(As), bBase = smem_u32(Bs), xBase = smem_u32(Xs);

    float acc[2][8][4];
#pragma unroll
    for (int mf = 0; mf < 2; mf++)
#pragma unroll
        for (int nf = 0; nf < 8; nf++)
#pragma unroll
            for (int q = 0; q < 4; q++) acc[mf][nf][q] = 0.0f;

    const int rA = l & 15;
    const int ksA = (l >> 4) & 1;
    const int nAdd = (l & 7) + ((l >> 4) << 3);
    const int kAdd = ((l >> 3) & 1) << 3;

#define DO_PASS(AB, BB)                                                          \
    _Pragma("unroll")                                                            \
    for (int ks = 0; ks < 8; ks++) {                                             \
        const int k0 = ks * 16;                                                  \
        uint32_t ra[2][4];                                                       \
        _Pragma("unroll")                                                        \
        for (int mf = 0; mf < 2; mf++) {                                         \
            int r = wm * 32 + mf * 16 + rA;                                      \
            uint32_t off = ((uint32_t)r << 8) + (uint32_t)((k0 + ksA * 8) << 1); \
            off ^= (r & 7) << 4;                                                 \
            LDSM_X4(ra[mf], (AB) + off);                                         \
        }                                                                        \
        uint32_t rb[4][4];                                                       \
        _Pragma("unroll")                                                        \
        for (int q = 0; q < 4; q++) {                                            \
            int n = wn * 64 + q * 16 + nAdd;                                     \
            uint32_t off = ((uint32_t)n << 8) + (uint32_t)((k0 + kAdd) << 1);    \
            off ^= (n & 7) << 4;                                                 \
            LDSM_X4(rb[q], (BB) + off);                                          \
        }                                                                        \
        _Pragma("unroll")                                                        \
        for (int mf = 0; mf < 2; mf++)                                           \
            _Pragma("unroll")                                                    \
            for (int q = 0; q < 4; q++) {                                        \
                mma16816(acc[mf][2 * q],     ra[mf], rb[q][0], rb[q][1]);        \
                mma16816(acc[mf][2 * q + 1], ra[mf], rb[q][2], rb[q][3]);        \
            }                                                                    \
    }

    DO_PASS(aBase, bBase);   // ah * bh
    DO_PASS(aBase, xBase);   // ah * bl
    __syncthreads();
    {
        const uint4* Al = (const uint4*)g_hmid_lo + (size_t)rowBase * 16;
        for (int i = tid; i < 2048; i += 256) {
            int r = i >> 4, kk = i & 15;
            uint32_t off = ((uint32_t)r << 8) + ((uint32_t)kk << 4);
            off ^= (r & 7) << 4;
            *(uint4*)(Xs + off) = Al[i];
        }
    }
    __syncthreads();
    DO_PASS(xBase, bBase);   // al * bh
#undef DO_PASS

    // ---- epilogue: reuse SMEM for x gather + per-row message reduction ----
    __syncthreads();                       // all ldmatrix reads done
    float* xs = (float*)sm;                // [128][128] = 64 KB
    float* smsg = (float*)(sm + 65536);    // [128]
    if (tid < 128) smsg[tid] = 0.0f;
    {
        int r = tid >> 1, jh = (tid & 1) * 64;
        int src = node_in[rowBase + r];
        const float4* xr = (const float4*)&g_h[(size_t)src * 128 + jh];
        float4* dp = (float4*)&xs[r * 128 + jh];
#pragma unroll
        for (int q = 0; q < 16; q++) dp[q] = xr[q];
    }
    __syncthreads();

#pragma unroll
    for (int mf = 0; mf < 2; mf++) {
        int r0 = wm * 32 + mf * 16 + (l >> 2);
        int row = rowBase + r0;
        float p0 = 0.0f, p1 = 0.0f;
#pragma unroll
        for (int nf = 0; nf < 8; nf++) {
            int cl = wn * 64 + nf * 8 + (l & 3) * 2;
            int col = colBase + cl;
            float b0 = bias[col], b1 = bias[col + 1];
            float t00 = acc[mf][nf][0] + b0, t01 = acc[mf][nf][1] + b1;
            float t10 = acc[mf][nf][2] + b0, t11 = acc[mf][nf][3] + b1;
            __stcs((float2*)&g_transform[(size_t)row * 16384 + col], make_float2(t00, t01));
            __stcs((float2*)&g_transform[(size_t)(row + 8) * 16384 + col], make_float2(t10, t11));
            p0 += t00 * xs[r0 * 128 + cl] + t01 * xs[r0 * 128 + cl + 1];
            p1 += t10 * xs[(r0 + 8) * 128 + cl] + t11 * xs[(r0 + 8) * 128 + cl + 1];
        }
        p0 += __shfl_xor_sync(0xffffffffu, p0, 1);
        p0 += __shfl_xor_sync(0xffffffffu, p0, 2);
        p1 += __shfl_xor_sync(0xffffffffu, p1, 1);
        p1 += __shfl_xor_sync(0xffffffffu, p1, 2);
        if ((l & 3) == 0) { atomicAdd(&smsg[r0], p0); atomicAdd(&smsg[r0 + 8], p1); }
    }
    __syncthreads();
    if (tid < 128) {
        int dst = node_out[rowBase + tid];
        atomicAdd(&g_upd[(size_t)dst * 128 + blockIdx.x], smsg[tid]);
    }
}

// ---------------- message (layers 2,3): per-edge matvec + scatter ------------
__global__ void k_message(const int* __restrict__ node_in, const int* __restrict__ node_out) {
    int e = blockIdx.x, t = threadIdx.x;
    __shared__ float v[Hd];
    int src = node_in[e];
    v[t] = g_h[src * Hd + t];
    __syncthreads();
    int lane = t & 31, w = t >> 5;
    int dst = node_out[e];
    const float* T = &g_transform[(size_t)e * 16384];
    float v0 = v[lane * 4 + 0], v1 = v[lane * 4 + 1], v2 = v[lane * 4 + 2], v3 = v[lane * 4 + 3];
#pragma unroll
    for (int r = w; r < Hd; r += 4) {
        float4 tv = __ldcs((const float4*)&T[r * Hd + lane * 4]);
        float s = tv.x * v0 + tv.y * v1 + tv.z * v2 + tv.w * v3;
#pragma unroll
        for (int o = 16; o; o >>= 1) s += __shfl_down_sync(0xffffffffu, s, o);
        if (lane == 0) atomicAdd(&g_upd[dst * Hd + r], s);
    }
}

// ---------------- GRU: 8 nodes per block; re-zeroes g_upd --------------------
__global__ void __launch_bounds__(128) k_gru(const float* __restrict__ b_ih,
                                             const float* __restrict__ b_hh) {
    int n0 = blockIdx.x * 8;
    int t = threadIdx.x;
    __shared__ float xs[8][Hd];
    __shared__ float hs[8][Hd];
#pragma unroll
    for (int q = 0; q < 8; q++) {
        xs[q][t] = fmaxf(g_upd[(n0 + q) * Hd + t], 0.0f);
        g_upd[(n0 + q) * Hd + t] = 0.0f;
        hs[q][t] = g_h[(n0 + q) * Hd + t];
    }
    __syncthreads();
    float ir[8], iz[8], in_[8], hr[8], hz[8], hn[8];
    float bir = b_ih[t], biz = b_ih[128 + t], bin = b_ih[256 + t];
    float bhr = b_hh[t], bhz = b_hh[128 + t], bhn = b_hh[256 + t];
#pragma unroll
    for (int q = 0; q < 8; q++) { ir[q] = bir; iz[q] = biz; in_[q] = bin; hr[q] = bhr; hz[q] = bhz; hn[q] = bhn; }
    for (int j = 0; j < Hd; j++) {
        float wi0 = g_wihT[j * 384 + t], wi1 = g_wihT[j * 384 + 128 + t], wi2 = g_wihT[j * 384 + 256 + t];
        float wh0 = g_whhT[j * 384 + t], wh1 = g_whhT[j * 384 + 128 + t], wh2 = g_whhT[j * 384 + 256 + t];
#pragma unroll
        for (int q = 0; q < 8; q++) {
            float x = xs[q][j], h = hs[q][j];
            ir[q] += x * wi0; iz[q] += x * wi1; in_[q] += x * wi2;
            hr[q] += h * wh0; hz[q] += h * wh1; hn[q] += h * wh2;
        }
    }
#pragma unroll
    for (int q = 0; q < 8; q++) {
        float r = sigm(ir[q] + hr[q]);
        float z = sigm(iz[q] + hz[q]);
        float nn = tanhf(in_[q] + r * hn[q]);
        g_h[(n0 + q) * Hd + t] = (1.0f - z) * nn + z * hs[q][t];
    }
}

// ---------------- LSTM step (Set2Set) ----------------
__global__ void k_lstm(const float* __restrict__ b_ih, const float* __restrict__ b_hh) {
    int b = blockIdx.x, t = threadIdx.x;
    __shared__ float qs[256];
    __shared__ float hsm[Hd];
    qs[t] = g_qs[b * 256 + t];
    qs[128 + t] = g_qs[b * 256 + 128 + t];
    hsm[t] = g_hs[b * Hd + t];
    __syncthreads();
    float gi = b_ih[t] + b_hh[t];
    float gf = b_ih[128 + t] + b_hh[128 + t];
    float gg = b_ih[256 + t] + b_hh[256 + t];
    float go = b_ih[384 + t] + b_hh[384 + t];
    for (int j = 0; j < 256; j++) {
        float q = qs[j];
        const float* wi = &g_lihT[j * 512];
        gi += q * wi[t]; gf += q * wi[128 + t]; gg += q * wi[256 + t]; go += q * wi[384 + t];
    }
    for (int j = 0; j < Hd; j++) {
        float h = hsm[j];
        const float* wh = &g_lhhT[j * 512];
        gi += h * wh[t]; gf += h * wh[128 + t]; gg += h * wh[256 + t]; go += h * wh[384 + t];
    }
    float c = sigm(gf) * g_cs[b * Hd + t] + sigm(gi) * tanhf(gg);
    float h = sigm(go) * tanhf(c);
    g_cs[b * Hd + t] = c;
    g_hs[b * Hd + t] = h;
}

// ---------------- attention + pooled (exact online segment softmax) ----------
__global__ void k_attend(const int* __restrict__ n2g) {
    int b = blockIdx.x, t = threadIdx.x;
    __shared__ float hsm[Hd];
    __shared__ float red[4];
    __shared__ int seg[2];
    hsm[t] = g_hs[b * Hd + t];
    if (t == 0) {
        int lo = 0, hi = Nn;
        while (lo < hi) { int m = (lo + hi) >> 1; if (n2g[m] < b) lo = m + 1; else hi = m; }
        seg[0] = lo;
        int lo2 = lo, hi2 = Nn;
        while (lo2 < hi2) { int m = (lo2 + hi2) >> 1; if (n2g[m] < b + 1) lo2 = m + 1; else hi2 = m; }
        seg[1] = lo2;
    }
    __syncthreads();
    int lo = seg[0], hi = seg[1];
    float m = -INFINITY, s = 0.0f, pool = 0.0f;
    for (int idx = lo; idx < hi; idx++) {
        float nf = g_h[(size_t)idx * Hd + t];
        float part = hsm[t] * nf;
#pragma unroll
        for (int o = 16; o; o >>= 1) part += __shfl_down_sync(0xffffffffu, part, o);
        if ((t & 31) == 0) red[t >> 5] = part;
        __syncthreads();
        float p = red[0] + red[1] + red[2] + red[3];
        __syncthreads();
        float mn = fmaxf(m, p);
        float corr = expf(m - mn);
        float w = expf(p - mn);
        s = s * corr + w;
        pool = pool * corr + w * nf;
        m = mn;
    }
    float pooled = (s > 0.0f) ? pool / s : 0.0f;
    g_qs[b * 256 + t] = hsm[t];
    g_qs[b * 256 + 128 + t] = pooled;
}

// ---------------- final output ----------------
__global__ void k_copy_out(float* __restrict__ out) {
    int i = blockIdx.x * blockDim.x + threadIdx.x;
    if (i < Bg * 256) out[i] = g_qs[i];
    else if (i < Bg * 256 + Nn * Hd) out[i] = g_h[i - Bg * 256];
}

extern "C" void kernel_launch(void* const* d_in, const int* in_sizes, int n_in,
                              void* d_out, int out_size) {
    const int*   unit_type    = (const int*)d_in[0];
    const int*   node_in      = (const int*)d_in[1];
    const int*   node_out     = (const int*)d_in[2];
    const int*   node2graph   = (const int*)d_in[3];
    const float* edge_feature = (const float*)d_in[4];
    const float* embedding    = (const float*)d_in[5];
    const float* mlp_w1       = (const float*)d_in[6];
    const float* mlp_b1       = (const float*)d_in[7];
    const float* mlp_w2       = (const float*)d_in[8];
    const float* mlp_b2       = (const float*)d_in[9];
    const float* gru_w_ih     = (const float*)d_in[10];
    const float* gru_w_hh     = (const float*)d_in[11];
    const float* gru_b_ih     = (const float*)d_in[12];
    const float* gru_b_hh     = (const float*)d_in[13];
    const float* lstm_w_ih    = (const float*)d_in[14];
    const float* lstm_w_hh    = (const float*)d_in[15];
    const float* lstm_b_ih    = (const float*)d_in[16];
    const float* lstm_b_hh    = (const float*)d_in[17];

    cudaFuncSetAttribute(k_gemm_mma, cudaFuncAttributeMaxDynamicSharedMemorySize, 98304);

    k_init_h<<<Nn, Hd>>>(unit_type, embedding);
    k_prep<<<8128, 256>>>(mlp_w2, gru_w_ih, gru_w_hh, lstm_w_ih, lstm_w_hh);
    k_edge_hidden<<<Ee, Hd>>>(edge_feature, mlp_w1, mlp_b1);
    // GEMM + fused layer-1 message (g_upd pre-zeroed by k_prep)
    k_gemm_mma<<<dim3(128, 128), 256, 98304>>>(mlp_b2, node_in, node_out);
    k_gru<<<Nn / 8, Hd>>>(gru_b_ih, gru_b_hh);

    for (int l = 1; l < 3; l++) {
        k_message<<<Ee, Hd>>>(node_in, node_out);
        k_gru<<<Nn / 8, Hd>>>(gru_b_ih, gru_b_hh);
    }

    for (int s = 0; s < 3; s++) {
        k_lstm<<<Bg, Hd>>>(lstm_b_ih, lstm_b_hh);
        k_attend<<<Bg, Hd>>>(node2graph);
    }

    int total = Bg * 256 + Nn * Hd;
    k_copy_out<<<(total + 255) / 256, 256>>>((float*)d_out);
}